// round 3
// baseline (speedup 1.0000x reference)
#include <cuda_runtime.h>
#include <cstdint>

#define S_LEN 16384
#define D_DIM 256
#define V_DIM 8
#define K_HEADS 24

__device__ __forceinline__ unsigned long long packf2(float lo, float hi) {
    unsigned long long r;
    asm("mov.b64 %0, {%1, %2};" : "=l"(r) : "f"(lo), "f"(hi));
    return r;
}
__device__ __forceinline__ void unpackf2(unsigned long long p, float& lo, float& hi) {
    asm("mov.b64 {%0, %1}, %2;" : "=f"(lo), "=f"(hi) : "l"(p));
}
// d += a*b packed f32x2 (2x fp32 FMA throughput on sm_100+)
__device__ __forceinline__ void fmaf2(unsigned long long& d, unsigned long long a,
                                      unsigned long long b) {
    asm("fma.rn.f32x2 %0, %1, %2, %0;" : "+l"(d) : "l"(a), "l"(b));
}
__device__ __forceinline__ unsigned long long addf2(unsigned long long a,
                                                    unsigned long long b) {
    unsigned long long r;
    asm("add.rn.f32x2 %0, %1, %2;" : "=l"(r) : "l"(a), "l"(b));
    return r;
}
__device__ __forceinline__ unsigned long long shfl_xor64(unsigned long long v, int m) {
    float lo, hi;
    unpackf2(v, lo, hi);
    lo = __shfl_xor_sync(0xffffffffu, lo, m);
    hi = __shfl_xor_sync(0xffffffffu, hi, m);
    return packf2(lo, hi);
}

__global__ __launch_bounds__(256, 2)
void attr_decoder_kernel(const float* __restrict__ feats,      // [N, 256]
                         const int*   __restrict__ mask_idx,   // [24, 16384]
                         const float* __restrict__ Wh,         // [24, 256, 8]
                         const float* __restrict__ bias,       // [24, 8]
                         float*       __restrict__ out)        // [24, 16384, 8]
{
    const int k    = blockIdx.y;
    const int lane = threadIdx.x & 31;
    const int warp = threadIdx.x >> 5;
    const int s0   = blockIdx.x * 256 + warp * 32;   // 32 rows per warp

    const int b4 = (lane >> 4) & 1;
    const int b3 = (lane >> 3) & 1;
    const int b2 = (lane >> 2) & 1;
    const int perm = 2 * b4 + b3;                    // v-pair permutation
    const int vown = 4 * b4 + 2 * b3 + b2;           // v this lane finally owns

    // ---- Per-head weights in registers, PRE-PERMUTED so the fold needs no selects.
    // Slot s holds v-pair q = s ^ perm; intra-pair (lo,hi) swapped when b2=1.
    // Lane owns d = lane*8 + i, i in [0,8).
    unsigned long long wp[8][4];
    const float4* wk = (const float4*)(Wh + (size_t)k * (D_DIM * V_DIM));
    #pragma unroll
    for (int i = 0; i < 8; ++i) {
        int d = lane * 8 + i;
        float4 A = wk[d * 2 + 0];
        float4 B = wk[d * 2 + 1];
        float pv[4][2] = {{A.x, A.y}, {A.z, A.w}, {B.x, B.y}, {B.z, B.w}};
        #pragma unroll
        for (int s = 0; s < 4; ++s) {
            int q = s ^ perm;
            float lo = pv[q][b2];
            float hi = pv[q][1 - b2];
            wp[i][s] = packf2(lo, hi);
        }
    }
    const float bias_v = bias[k * V_DIM + vown];

    // One gather index per lane covers the warp's 32 rows.
    const int idxv = mask_idx[(size_t)k * S_LEN + s0 + lane];

    // Prefetch row 0
    int i0 = __shfl_sync(0xffffffffu, idxv, 0);
    const float4* fr0 = (const float4*)(feats + (size_t)i0 * D_DIM) + lane * 2;
    float4 fa = fr0[0];
    float4 fb = fr0[1];

    float keepval = 0.0f;

    #pragma unroll 4
    for (int r = 0; r < 32; ++r) {
        const float4 ca = fa, cb = fb;
        // Software prefetch next row (hides L2/DRAM gather latency)
        if (r + 1 < 32) {
            int ni = __shfl_sync(0xffffffffu, idxv, r + 1);
            const float4* nf = (const float4*)(feats + (size_t)ni * D_DIM) + lane * 2;
            fa = nf[0];
            fb = nf[1];
        }

        // ---- Packed FMA: acc2[s] = partial v-pair (slot s) over this lane's 8 d's.
        const float f[8] = {ca.x, ca.y, ca.z, ca.w, cb.x, cb.y, cb.z, cb.w};
        unsigned long long acc2[4] = {0ull, 0ull, 0ull, 0ull};
        #pragma unroll
        for (int i = 0; i < 8; ++i) {
            unsigned long long fd = packf2(f[i], f[i]);
            #pragma unroll
            for (int s = 0; s < 4; ++s) fmaf2(acc2[s], fd, wp[i][s]);
        }

        // ---- Select-free fold (weights were pre-permuted):
        // stage off16: 4 pairs -> 2 pairs
        unsigned long long t0 = addf2(acc2[0], shfl_xor64(acc2[2], 16));
        unsigned long long t1 = addf2(acc2[1], shfl_xor64(acc2[3], 16));
        // stage off8: 2 pairs -> 1 pair (pair q = perm, i.e. v = {2perm, 2perm+1})
        unsigned long long u2 = addf2(t0, shfl_xor64(t1, 8));
        // stage off4: intra-pair; lo = v_own, hi = partner's v (pre-swapped by b2)
        float lo, hi;
        unpackf2(u2, lo, hi);
        float w = lo + __shfl_xor_sync(0xffffffffu, hi, 4);
        // remaining lanes (bits 1,0): plain butterflies
        w += __shfl_xor_sync(0xffffffffu, w, 2);
        w += __shfl_xor_sync(0xffffffffu, w, 1);
        const float res = w + bias_v;   // lane l holds v = vown, replica over l&3

        // Buffer 4 rows (replica (lane&3) keeps row rbase+(lane&3)),
        // then one coalesced, lane-permuted 128B warp store.
        if ((lane & 3) == (r & 3)) keepval = res;
        if ((r & 3) == 3) {
            out[((size_t)k * S_LEN + s0 + (r - 3) + (lane & 3)) * V_DIM + vown] = keepval;
        }
    }
}

extern "C" void kernel_launch(void* const* d_in, const int* in_sizes, int n_in,
                              void* d_out, int out_size) {
    // metadata order: block_type_grid (unused), features, mask_idx, head_weights, head_bias
    const float* feats    = (const float*)d_in[1];
    const int*   mask_idx = (const int*)  d_in[2];
    const float* Wh       = (const float*)d_in[3];
    const float* bias     = (const float*)d_in[4];
    float*       out      = (float*)d_out;

    dim3 grid(S_LEN / 256, K_HEADS);   // 64 x 24 blocks, 8 warps each, 32 rows/warp
    attr_decoder_kernel<<<grid, 256>>>(feats, mask_idx, Wh, bias, out);
}